// round 2
// baseline (speedup 1.0000x reference)
#include <cuda_runtime.h>
#include <math.h>

// Problem constants
#define B_    128
#define S_    256
#define D_    1536
#define DIN_  768
#define NH_   8
#define DH_   192
#define FF_   2048
#define BS_   (B_*S_)   // 32768

// ---------------- scratch (device globals; no cudaMalloc allowed) -------------
__device__ float g_t0 [B_*D_];
__device__ float g_v  [B_*D_];
__device__ float g_sa [B_*D_];
__device__ float g_t1 [B_*D_];
__device__ float g_qp [B_*D_];
__device__ float g_g  [B_*NH_*D_];
__device__ float g_scores[B_*NH_*S_];
__device__ float g_mt [B_*NH_*D_];
__device__ float g_o  [B_*D_];
__device__ float g_ca [B_*D_];
__device__ float g_t2 [B_*D_];
__device__ float g_h1 [B_*FF_];
__device__ float g_ff [B_*D_];
__device__ float g_t3 [B_*D_];
__device__ float g_xsq[B_*D_];
__device__ float g_qp2[B_*D_];
__device__ float g_qt [B_*D_];
__device__ float g_A  [2*B_*D_];
__device__ float g_S  [(size_t)2*B_*BS_];
__device__ float g_nm [B_*S_];
__device__ float g_nx [B_];

// ---------------- packed f32x2 helpers ------------------------------------------
__device__ __forceinline__ unsigned long long fma2(unsigned long long a,
                                                   unsigned long long b,
                                                   unsigned long long c)
{
    unsigned long long d;
    asm("fma.rn.f32x2 %0, %1, %2, %3;" : "=l"(d) : "l"(a), "l"(b), "l"(c));
    return d;
}
__device__ __forceinline__ float2 upk(unsigned long long u)
{
    float2 f;
    asm("mov.b64 {%0,%1}, %2;" : "=f"(f.x), "=f"(f.y) : "l"(u));
    return f;
}

// ---------------- f32x2 tiled GEMM: C = A(M,K) @ W(N,K)^T + bias ----------------
// acc pairs along M rows; W duplicated in smem so FFMA2 operands load natively.
template<int BM,int BN,int BK,int TM,int TN,int NT,bool RELU>
__global__ void __launch_bounds__(NT) gemm_nt2(
    const float* __restrict__ A, int lda, long long strideA,
    const float* __restrict__ W, int ldw, long long strideW,
    const float* __restrict__ bias, int strideBias,
    float* __restrict__ C, int ldc, long long strideC, int K)
{
    A += (long long)blockIdx.z * strideA;
    W += (long long)blockIdx.z * strideW;
    C += (long long)blockIdx.z * strideC;
    if (bias) bias += (long long)blockIdx.z * strideBias;

    __shared__ float sA [BK][BM];
    __shared__ float sWd[BK][2*BN];
    const int tid = threadIdx.x;
    const int bm = blockIdx.y*BM, bn = blockIdx.x*BN;
    const int tx = tid % (BN/TN), ty = tid / (BN/TN);

    unsigned long long acc[TM/2][TN];
    #pragma unroll
    for (int i=0;i<TM/2;i++)
        #pragma unroll
        for (int j=0;j<TN;j++) acc[i][j]=0ull;

    for (int k0=0;k0<K;k0+=BK) {
        #pragma unroll
        for (int i=tid;i<BM*(BK/4);i+=NT) {
            int r=i/(BK/4), kv=i%(BK/4);
            float4 v=*(const float4*)(A+(size_t)(bm+r)*lda + k0 + kv*4);
            sA[kv*4+0][r]=v.x; sA[kv*4+1][r]=v.y; sA[kv*4+2][r]=v.z; sA[kv*4+3][r]=v.w;
        }
        #pragma unroll
        for (int i=tid;i<BN*(BK/4);i+=NT) {
            int r=i/(BK/4), kv=i%(BK/4);
            float4 v=*(const float4*)(W+(size_t)(bn+r)*ldw + k0 + kv*4);
            *(float2*)&sWd[kv*4+0][2*r] = make_float2(v.x,v.x);
            *(float2*)&sWd[kv*4+1][2*r] = make_float2(v.y,v.y);
            *(float2*)&sWd[kv*4+2][2*r] = make_float2(v.z,v.z);
            *(float2*)&sWd[kv*4+3][2*r] = make_float2(v.w,v.w);
        }
        __syncthreads();
        #pragma unroll
        for (int kk=0;kk<BK;kk++) {
            unsigned long long a2[TM/2], b2[TN];
            #pragma unroll
            for (int i=0;i<TM/2;i+=2) {
                ulonglong2 p=*(const ulonglong2*)&sA[kk][ty*TM + 4*(i/2)*1 + 0 + i*0];
                // (address = sA[kk][ty*TM + 2*i]) — keep simple & correct:
                p=*(const ulonglong2*)&sA[kk][ty*TM + 2*i];
                a2[i]=p.x; a2[i+1]=p.y;
            }
            #pragma unroll
            for (int j=0;j<TN;j+=2) {
                ulonglong2 q=*(const ulonglong2*)&sWd[kk][2*(tx*TN+j)];
                b2[j]=q.x; b2[j+1]=q.y;
            }
            #pragma unroll
            for (int i=0;i<TM/2;i++)
                #pragma unroll
                for (int j=0;j<TN;j++) acc[i][j]=fma2(a2[i],b2[j],acc[i][j]);
        }
        __syncthreads();
    }
    #pragma unroll
    for (int i=0;i<TM/2;i++) {
        int gm0 = bm + ty*TM + 2*i;
        float o0[TN], o1[TN];
        #pragma unroll
        for (int j=0;j<TN;j++) {
            float2 f = upk(acc[i][j]);
            float bz = bias ? bias[bn + tx*TN + j] : 0.f;
            o0[j]=f.x+bz; o1[j]=f.y+bz;
            if (RELU){ o0[j]=fmaxf(o0[j],0.f); o1[j]=fmaxf(o1[j],0.f); }
        }
        #pragma unroll
        for (int j=0;j<TN;j+=4) {
            *(float4*)&C[(size_t)gm0    *ldc + bn + tx*TN + j] = *(float4*)&o0[j];
            *(float4*)&C[(size_t)(gm0+1)*ldc + bn + tx*TN + j] = *(float4*)&o1[j];
        }
    }
}

// ---------------- f32x2 tiled GEMM: C = A(M,K) @ W(K,N) + bias ------------------
template<int BM,int BN,int BK,int TM,int TN,int NT>
__global__ void __launch_bounds__(NT) gemm_nn2(
    const float* __restrict__ A, int lda, long long strideA,
    const float* __restrict__ W, int ldw, long long strideW,
    const float* __restrict__ bias, int strideBias,
    float* __restrict__ C, int ldc, long long strideC, int K)
{
    A += (long long)blockIdx.z * strideA;
    W += (long long)blockIdx.z * strideW;
    C += (long long)blockIdx.z * strideC;
    if (bias) bias += (long long)blockIdx.z * strideBias;

    __shared__ float sA [BK][BM];
    __shared__ float sWd[BK][2*BN];
    const int tid = threadIdx.x;
    const int bm = blockIdx.y*BM, bn = blockIdx.x*BN;
    const int tx = tid % (BN/TN), ty = tid / (BN/TN);

    unsigned long long acc[TM/2][TN];
    #pragma unroll
    for (int i=0;i<TM/2;i++)
        #pragma unroll
        for (int j=0;j<TN;j++) acc[i][j]=0ull;

    for (int k0=0;k0<K;k0+=BK) {
        #pragma unroll
        for (int i=tid;i<BM*(BK/4);i+=NT) {
            int r=i/(BK/4), kv=i%(BK/4);
            float4 v=*(const float4*)(A+(size_t)(bm+r)*lda + k0 + kv*4);
            sA[kv*4+0][r]=v.x; sA[kv*4+1][r]=v.y; sA[kv*4+2][r]=v.z; sA[kv*4+3][r]=v.w;
        }
        #pragma unroll
        for (int i=tid;i<BK*(BN/4);i+=NT) {
            int kk=i/(BN/4), nv=i%(BN/4);
            float4 v=*(const float4*)(W+(size_t)(k0+kk)*ldw + bn + nv*4);
            *(float2*)&sWd[kk][2*(nv*4+0)] = make_float2(v.x,v.x);
            *(float2*)&sWd[kk][2*(nv*4+1)] = make_float2(v.y,v.y);
            *(float2*)&sWd[kk][2*(nv*4+2)] = make_float2(v.z,v.z);
            *(float2*)&sWd[kk][2*(nv*4+3)] = make_float2(v.w,v.w);
        }
        __syncthreads();
        #pragma unroll
        for (int kk=0;kk<BK;kk++) {
            unsigned long long a2[TM/2], b2[TN];
            #pragma unroll
            for (int i=0;i<TM/2;i+=2) {
                ulonglong2 p=*(const ulonglong2*)&sA[kk][ty*TM + 2*i];
                a2[i]=p.x; a2[i+1]=p.y;
            }
            #pragma unroll
            for (int j=0;j<TN;j+=2) {
                ulonglong2 q=*(const ulonglong2*)&sWd[kk][2*(tx*TN+j)];
                b2[j]=q.x; b2[j+1]=q.y;
            }
            #pragma unroll
            for (int i=0;i<TM/2;i++)
                #pragma unroll
                for (int j=0;j<TN;j++) acc[i][j]=fma2(a2[i],b2[j],acc[i][j]);
        }
        __syncthreads();
    }
    #pragma unroll
    for (int i=0;i<TM/2;i++) {
        int gm0 = bm + ty*TM + 2*i;
        float o0[TN], o1[TN];
        #pragma unroll
        for (int j=0;j<TN;j++) {
            float2 f = upk(acc[i][j]);
            float bz = bias ? bias[bn + tx*TN + j] : 0.f;
            o0[j]=f.x+bz; o1[j]=f.y+bz;
        }
        #pragma unroll
        for (int j=0;j<TN;j+=4) {
            *(float4*)&C[(size_t)gm0    *ldc + bn + tx*TN + j] = *(float4*)&o0[j];
            *(float4*)&C[(size_t)(gm0+1)*ldc + bn + tx*TN + j] = *(float4*)&o1[j];
        }
    }
}

// ---------------- LayerNorm(+residual) over rows of length D_ ------------------
__global__ void __launch_bounds__(256) ln_kernel(
    const float* __restrict__ a, const float* __restrict__ r,
    const float* __restrict__ w, const float* __restrict__ bb,
    float* __restrict__ out, float* __restrict__ norm_out)
{
    const int row = blockIdx.x, tid = threadIdx.x;
    const float* ap = a + (size_t)row*D_;
    const float* rp = r ? r + (size_t)row*D_ : nullptr;
    float vals[6]; float s1=0.f, s2=0.f;
    #pragma unroll
    for (int i=0;i<6;i++) {
        int e = tid + i*256;
        float v = ap[e] + (rp ? rp[e] : 0.f);
        vals[i]=v; s1+=v; s2+=v*v;
    }
    __shared__ float red[16];
    int lane=tid&31, wid=tid>>5;
    for (int o=16;o;o>>=1){ s1+=__shfl_xor_sync(~0u,s1,o); s2+=__shfl_xor_sync(~0u,s2,o); }
    if (lane==0){ red[wid]=s1; red[8+wid]=s2; }
    __syncthreads();
    if (tid==0){ float a1=0,a2=0; for(int k=0;k<8;k++){a1+=red[k];a2+=red[8+k];} red[0]=a1; red[8]=a2; }
    __syncthreads();
    float mean = red[0]*(1.0f/D_);
    float var  = red[8]*(1.0f/D_) - mean*mean;
    float rstd = rsqrtf(var + 1e-5f);
    float ss = 0.f;
    #pragma unroll
    for (int i=0;i<6;i++) {
        int e = tid + i*256;
        float y = (vals[i]-mean)*rstd*w[e] + bb[e];
        out[(size_t)row*D_+e] = y;
        ss += y*y;
    }
    if (norm_out) {
        for (int o=16;o;o>>=1) ss+=__shfl_xor_sync(~0u,ss,o);
        __syncthreads();
        if (lane==0) red[wid]=ss;
        __syncthreads();
        if (tid==0){ float t=0; for(int k=0;k<8;k++) t+=red[k]; norm_out[row]=sqrtf(t); }
    }
}

// ---------------- CA: scores[b,h,s] = mem[b,s]·g[b,h] / sqrt(DH) ---------------
__global__ void __launch_bounds__(256) ca_scores_kernel(const float* __restrict__ mem)
{
    __shared__ float gs[NH_*D_];
    const int b = blockIdx.x, tid = threadIdx.x;
    const float4* gsrc = (const float4*)(g_g + (size_t)b*NH_*D_);
    for (int i=tid;i<NH_*D_/4;i+=256) ((float4*)gs)[i]=gsrc[i];
    __syncthreads();
    const int warp=tid>>5, lane=tid&31;
    const float* mb = mem + (size_t)b*S_*D_;
    const float scale = rsqrtf((float)DH_);
    const int sbase = blockIdx.y*128 + warp*16;
    for (int grp=0;grp<4;grp++) {
        int s0 = sbase + grp*4;
        float acc[NH_][4];
        #pragma unroll
        for (int h=0;h<NH_;h++)
            #pragma unroll
            for (int r2=0;r2<4;r2++) acc[h][r2]=0.f;
        #pragma unroll
        for (int i=0;i<12;i++) {
            int e = lane*4 + i*128;
            float4 m[4];
            #pragma unroll
            for (int r2=0;r2<4;r2++) m[r2]=*(const float4*)(mb+(size_t)(s0+r2)*D_+e);
            #pragma unroll
            for (int h=0;h<NH_;h++) {
                float4 gv=*(const float4*)(gs + h*D_ + e);
                #pragma unroll
                for (int r2=0;r2<4;r2++)
                    acc[h][r2] += gv.x*m[r2].x + gv.y*m[r2].y + gv.z*m[r2].z + gv.w*m[r2].w;
            }
        }
        #pragma unroll
        for (int h=0;h<NH_;h++)
            #pragma unroll
            for (int r2=0;r2<4;r2++) {
                float v=acc[h][r2];
                for (int o=16;o;o>>=1) v+=__shfl_xor_sync(~0u,v,o);
                if (lane==0) g_scores[((size_t)b*NH_+h)*S_ + s0+r2] = v*scale;
            }
    }
}

// ---------------- softmax over s (in place) ------------------------------------
__global__ void __launch_bounds__(256) ca_softmax_kernel()
{
    const int row=blockIdx.x, tid=threadIdx.x;
    float* sp = g_scores + (size_t)row*S_;
    float v = sp[tid];
    __shared__ float red[16];
    int lane=tid&31, wid=tid>>5;
    float m=v;
    for (int o=16;o;o>>=1) m=fmaxf(m,__shfl_xor_sync(~0u,m,o));
    if (lane==0) red[wid]=m;
    __syncthreads();
    if (tid==0){ float mm=red[0]; for(int k=1;k<8;k++) mm=fmaxf(mm,red[k]); red[0]=mm; }
    __syncthreads();
    m=red[0];
    float e=__expf(v-m);
    float s=e;
    for (int o=16;o;o>>=1) s+=__shfl_xor_sync(~0u,s,o);
    __syncthreads();
    if (lane==0) red[8+wid]=s;
    __syncthreads();
    if (tid==0){ float t=0; for(int k=0;k<8;k++) t+=red[8+k]; red[8]=t; }
    __syncthreads();
    sp[tid]=e/red[8];
}

// ---------------- m~[b,h] = sum_s attn[b,h,s] * mem[b,s,:] ---------------------
__global__ void __launch_bounds__(256) mtilde_kernel(const float* __restrict__ mem)
{
    __shared__ float at[NH_*S_];
    const int b=blockIdx.x, tid=threadIdx.x;
    for (int i=tid;i<NH_*S_;i+=256) at[i]=g_scores[(size_t)b*NH_*S_+i];
    __syncthreads();
    const int e = blockIdx.y*512 + tid*2;
    const float* mb = mem + (size_t)b*S_*D_;
    float2 acc[NH_];
    #pragma unroll
    for (int h=0;h<NH_;h++){ acc[h].x=0.f; acc[h].y=0.f; }
    for (int s=0;s<S_;s++) {
        float2 mv=*(const float2*)(mb+(size_t)s*D_+e);
        #pragma unroll
        for (int h=0;h<NH_;h++){
            float a=at[h*S_+s];
            acc[h].x=fmaf(a,mv.x,acc[h].x);
            acc[h].y=fmaf(a,mv.y,acc[h].y);
        }
    }
    #pragma unroll
    for (int h=0;h<NH_;h++)
        *(float2*)(g_mt + (size_t)b*NH_*D_ + h*D_ + e) = acc[h];
}

// ---------------- ||memory[j,s]|| ----------------------------------------------
__global__ void __launch_bounds__(256) nm_kernel(const float* __restrict__ mem)
{
    int row = blockIdx.x*8 + (threadIdx.x>>5);
    int lane = threadIdx.x&31;
    const float* p = mem + (size_t)row*D_;
    float s=0.f;
    for (int e=lane*4;e<D_;e+=128){ float4 v=*(const float4*)(p+e); s+=v.x*v.x+v.y*v.y+v.z*v.z+v.w*v.w; }
    for (int o=16;o;o>>=1) s+=__shfl_xor_sync(~0u,s,o);
    if (lane==0) g_nm[row]=sqrtf(s);
}

// ---------------- build A = [qt/sqrt(D) ; x_sq] --------------------------------
__global__ void prepA_kernel()
{
    int idx = blockIdx.x*256 + threadIdx.x;
    const float sc = rsqrtf((float)D_);
    g_A[idx] = g_qt[idx]*sc;
    g_A[B_*D_+idx] = g_xsq[idx];
}

// ---------------- final reduce: softmax_s(S) weighted cosine sum ---------------
__global__ void __launch_bounds__(256) pool_reduce_kernel(
    const float* __restrict__ ls, float* __restrict__ out)
{
    const int j=blockIdx.x, i=blockIdx.y, s=threadIdx.x;
    float Sv = g_S[(size_t)i*BS_ + j*S_ + s];
    float Cv = g_S[(size_t)(B_+i)*BS_ + j*S_ + s];
    float nmv = g_nm[j*S_+s];
    __shared__ float red[16];
    int lane=s&31, wid=s>>5;
    float m=Sv;
    for (int o=16;o;o>>=1) m=fmaxf(m,__shfl_xor_sync(~0u,m,o));
    if (lane==0) red[wid]=m;
    __syncthreads();
    if (s==0){ float mm=red[0]; for(int k=1;k<8;k++) mm=fmaxf(mm,red[k]); red[0]=mm; }
    __syncthreads();
    m=red[0];
    float e = expf(Sv-m);
    float t1=e, t2=e*Cv/nmv;
    for (int o=16;o;o>>=1){ t1+=__shfl_xor_sync(~0u,t1,o); t2+=__shfl_xor_sync(~0u,t2,o); }
    __syncthreads();
    if (lane==0){ red[wid]=t1; red[8+wid]=t2; }
    __syncthreads();
    if (s==0) {
        float Z=0.f, Wv=0.f;
        for (int k=0;k<8;k++){ Z+=red[k]; Wv+=red[8+k]; }
        float val = expf(ls[0]) * Wv / (Z * g_nx[i]);
        out[(size_t)i*B_ + j] = val;
        out[(size_t)B_*B_ + (size_t)j*B_ + i] = val;
    }
}

__global__ void copy_xsq_kernel(float* __restrict__ out)
{
    int idx = blockIdx.x*256 + threadIdx.x;
    out[(size_t)2*B_*B_ + idx] = g_xsq[idx];
}

// ---------------- host ----------------------------------------------------------
template<typename T> static float* sym(T& s){ void* p=nullptr; cudaGetSymbolAddress(&p, s); return (float*)p; }

extern "C" void kernel_launch(void* const* d_in, const int* in_sizes, int n_in,
                              void* d_out, int out_size)
{
    const float* x        =(const float*)d_in[0];
    const float* mem      =(const float*)d_in[1];
    const float* emb_w    =(const float*)d_in[2];
    const float* emb_b    =(const float*)d_in[3];
    const float* sa_in_w  =(const float*)d_in[4];
    const float* sa_in_b  =(const float*)d_in[5];
    const float* sa_out_w =(const float*)d_in[6];
    const float* sa_out_b =(const float*)d_in[7];
    const float* ca_in_w  =(const float*)d_in[8];
    const float* ca_in_b  =(const float*)d_in[9];
    const float* ca_out_w =(const float*)d_in[10];
    const float* ca_out_b =(const float*)d_in[11];
    const float* lin1_w   =(const float*)d_in[12];
    const float* lin1_b   =(const float*)d_in[13];
    const float* lin2_w   =(const float*)d_in[14];
    const float* lin2_b   =(const float*)d_in[15];
    const float* ln1_w    =(const float*)d_in[16];
    const float* ln1_b    =(const float*)d_in[17];
    const float* ln2_w    =(const float*)d_in[18];
    const float* ln2_b    =(const float*)d_in[19];
    const float* ln3_w    =(const float*)d_in[20];
    const float* ln3_b    =(const float*)d_in[21];
    const float* fin_w    =(const float*)d_in[22];
    const float* fin_b    =(const float*)d_in[23];
    const float* attn_in_w=(const float*)d_in[24];
    const float* attn_in_b=(const float*)d_in[25];
    const float* logit_sc =(const float*)d_in[26];
    float* out = (float*)d_out;

    float* t0 = sym(g_t0);  float* v   = sym(g_v);   float* sa  = sym(g_sa);
    float* t1 = sym(g_t1);  float* qp  = sym(g_qp);  float* gg  = sym(g_g);
    float* mt = sym(g_mt);  float* o   = sym(g_o);   float* ca  = sym(g_ca);
    float* t2 = sym(g_t2);  float* h1  = sym(g_h1);  float* ff  = sym(g_ff);
    float* t3 = sym(g_t3);  float* xsq = sym(g_xsq); float* qp2 = sym(g_qp2);
    float* qt = sym(g_qt);  float* Am  = sym(g_A);   float* Sm  = sym(g_S);
    float* nx = sym(g_nx);

    // small-GEMM config: BM=32,BN=64,BK=16,TM=4,TN=8,NT=64
    #define SGEMM_NT(GX,GY,GZ, A_,LDA,SA_, W_,LDW,SW_, B_P,SB_, C_,LDC,SC_, K_, RELU_) \
        gemm_nt2<32,64,16,4,8,64,RELU_><<<dim3(GX,GY,GZ), 64>>>(A_,LDA,SA_, W_,LDW,SW_, B_P,SB_, C_,LDC,SC_, K_)
    #define SGEMM_NN(GX,GY,GZ, A_,LDA,SA_, W_,LDW,SW_, B_P,SB_, C_,LDC,SC_, K_) \
        gemm_nn2<32,64,16,4,8,64><<<dim3(GX,GY,GZ), 64>>>(A_,LDA,SA_, W_,LDW,SW_, B_P,SB_, C_,LDC,SC_, K_)

    // 1. t0 = x @ emb_w.T + emb_b
    SGEMM_NT(D_/64, B_/32, 1, x, DIN_, 0, emb_w, DIN_, 0, emb_b, 0, t0, D_, 0, DIN_, false);
    // 2. SA (L=1): v = t0 @ wv.T + bv ; sa = v @ out_w.T + out_b
    SGEMM_NT(D_/64, B_/32, 1, t0, D_, 0, sa_in_w + (size_t)2*D_*D_, D_, 0, sa_in_b + 2*D_, 0, v, D_, 0, D_, false);
    SGEMM_NT(D_/64, B_/32, 1, v, D_, 0, sa_out_w, D_, 0, sa_out_b, 0, sa, D_, 0, D_, false);
    // 3. t1 = LN(t0 + sa)
    ln_kernel<<<B_, 256>>>(t0, sa, ln1_w, ln1_b, t1, nullptr);
    // 4. CA q-proj, then g[b,h] = qp_h @ wk_h  (batched over heads)
    SGEMM_NT(D_/64, B_/32, 1, t1, D_, 0, ca_in_w, D_, 0, ca_in_b, 0, qp, D_, 0, D_, false);
    SGEMM_NN(D_/64, B_/32, NH_, qp, D_, DH_,
             ca_in_w + (size_t)D_*D_, D_, (long long)DH_*D_,
             (const float*)nullptr, 0, gg, NH_*D_, D_, DH_);
    // 5. CA scores / softmax / weighted memory
    ca_scores_kernel<<<dim3(B_,2), 256>>>(mem);
    ca_softmax_kernel<<<B_*NH_, 256>>>();
    mtilde_kernel<<<dim3(B_,3), 256>>>(mem);
    // 6. o_h = m~_h @ wv_h.T + bv_h (batched) ; ca = o @ out_w.T + out_b
    SGEMM_NT(DH_/64, B_/32, NH_, mt, NH_*D_, D_,
             ca_in_w + (size_t)2*D_*D_, D_, (long long)DH_*D_,
             ca_in_b + 2*D_, DH_, o, D_, DH_, D_, false);
    SGEMM_NT(D_/64, B_/32, 1, o, D_, 0, ca_out_w, D_, 0, ca_out_b, 0, ca, D_, 0, D_, false);
    // 7. t2 = LN(t1 + ca)
    ln_kernel<<<B_, 256>>>(t1, ca, ln2_w, ln2_b, t2, nullptr);
    // 8. FF
    SGEMM_NT(FF_/64, B_/32, 1, t2, D_, 0, lin1_w, D_, 0, lin1_b, 0, h1, FF_, 0, D_, true);
    SGEMM_NT(D_/64, B_/32, 1, h1, FF_, 0, lin2_w, FF_, 0, lin2_b, 0, ff, D_, 0, FF_, false);
    // 9. t3 = LN(t2 + ff) ; x_sq = LN(t3) with row norm
    ln_kernel<<<B_, 256>>>(t2, ff, ln3_w, ln3_b, t3, nullptr);
    ln_kernel<<<B_, 256>>>(t3, nullptr, fin_w, fin_b, xsq, nx);
    // 10. pooling: qp2 = x_sq@wq2.T+bq2 ; qt = qp2@wk2 (bias cancels in softmax)
    SGEMM_NT(D_/64, B_/32, 1, xsq, D_, 0, attn_in_w, D_, 0, attn_in_b, 0, qp2, D_, 0, D_, false);
    SGEMM_NN(D_/64, B_/32, 1, qp2, D_, 0, attn_in_w + (size_t)D_*D_, D_, 0,
             (const float*)nullptr, 0, qt, D_, 0, D_);
    prepA_kernel<<<(B_*D_)/256, 256>>>();
    nm_kernel<<<BS_/8, 256>>>(mem);
    // 11. big GEMM: [qt/sqrt(D); x_sq] (256x1536) @ memory^T (1536x32768)
    gemm_nt2<128,128,16,8,8,256,false><<<dim3(BS_/128, 2*B_/128), 256>>>(
        Am, D_, 0, mem, D_, 0, (const float*)nullptr, 0, Sm, BS_, 0, D_);
    // 12. final softmax-weighted cosine reduce + transpose write
    pool_reduce_kernel<<<dim3(B_, B_), 256>>>(logit_sc, out);
    // 13. third output
    copy_xsq_kernel<<<(B_*D_)/256, 256>>>(out);

    (void)in_sizes; (void)n_in; (void)out_size;
}

// round 4
// speedup vs baseline: 4.5365x; 4.5365x over previous
#include <cuda_runtime.h>
#include <cuda_bf16.h>
#include <math.h>
#include <stdint.h>

// Problem constants
#define B_    128
#define S_    256
#define D_    1536
#define DIN_  768
#define NH_   8
#define DH_   192
#define FF_   2048
#define BS_   (B_*S_)   // 32768
#define KP_   3072      // hi||lo width = 2*D_

// ---------------- scratch (device globals; no cudaMalloc allowed) -------------
__device__ float g_t0 [B_*D_];
__device__ float g_v  [B_*D_];
__device__ float g_sa [B_*D_];
__device__ float g_t1 [B_*D_];
__device__ float g_qp [B_*D_];
__device__ float g_g  [B_*NH_*D_];
__device__ float g_scores[B_*NH_*S_];
__device__ float g_mt [B_*NH_*D_];
__device__ float g_o  [B_*D_];
__device__ float g_ca [B_*D_];
__device__ float g_t2 [B_*D_];
__device__ float g_h1 [B_*FF_];
__device__ float g_ff [B_*D_];
__device__ float g_t3 [B_*D_];
__device__ float g_xsq[B_*D_];
__device__ float g_qp2[B_*D_];
__device__ float g_qt [B_*D_];
__device__ float g_S  [(size_t)2*B_*BS_];
__device__ float g_nm [B_*S_];
__device__ float g_nx [B_];
__device__ float g_part[1600*1024];                 // K-split partials (6.4 MB)
__device__ __nv_bfloat16 g_mb[(size_t)BS_*KP_];     // memory hi||lo bf16
__device__ __nv_bfloat16 g_ab[256*KP_];             // A hi||lo bf16

// =================== small fp32 GEMMs + K-split ================================
template<int BM,int BN,int BK,int TM,int TN,bool RELU>
__global__ void __launch_bounds__(256) gemm_nt(
    const float* __restrict__ A, int lda, long long strideA,
    const float* __restrict__ W, int ldw, long long strideW,
    const float* __restrict__ bias, int strideBias,
    float* __restrict__ C, int ldc, long long strideC,
    int K, int KS, float* __restrict__ partial)
{
    const int zb = blockIdx.z / KS, chunk = blockIdx.z % KS;
    const int Kc = K / KS;
    A += (long long)zb*strideA + chunk*Kc;
    W += (long long)zb*strideW + chunk*Kc;
    C += (long long)zb*strideC;
    if (bias) bias += (long long)zb*strideBias;

    __shared__ float sA[BK][BM];
    __shared__ float sW[BK][BN];
    const int tid = threadIdx.x;
    const int bm = blockIdx.y*BM, bn = blockIdx.x*BN;
    const int tx = tid % (BN/TN), ty = tid / (BN/TN);
    float acc[TM][TN];
    #pragma unroll
    for (int i=0;i<TM;i++)
        #pragma unroll
        for (int j=0;j<TN;j++) acc[i][j]=0.f;

    for (int k0=0;k0<Kc;k0+=BK) {
        for (int i=tid;i<BM*(BK/4);i+=256) {
            int r=i/(BK/4), kv=i%(BK/4);
            float4 v=*(const float4*)(A+(size_t)(bm+r)*lda + k0 + kv*4);
            sA[kv*4+0][r]=v.x; sA[kv*4+1][r]=v.y; sA[kv*4+2][r]=v.z; sA[kv*4+3][r]=v.w;
        }
        for (int i=tid;i<BN*(BK/4);i+=256) {
            int r=i/(BK/4), kv=i%(BK/4);
            float4 v=*(const float4*)(W+(size_t)(bn+r)*ldw + k0 + kv*4);
            sW[kv*4+0][r]=v.x; sW[kv*4+1][r]=v.y; sW[kv*4+2][r]=v.z; sW[kv*4+3][r]=v.w;
        }
        __syncthreads();
        #pragma unroll
        for (int kk=0;kk<BK;kk++) {
            float a[TM], w[TN];
            #pragma unroll
            for (int i=0;i<TM;i+=4) *(float4*)&a[i] = *(const float4*)&sA[kk][ty*TM+i];
            #pragma unroll
            for (int j=0;j<TN;j+=4) *(float4*)&w[j] = *(const float4*)&sW[kk][tx*TN+j];
            #pragma unroll
            for (int i=0;i<TM;i++)
                #pragma unroll
                for (int j=0;j<TN;j++) acc[i][j] = fmaf(a[i], w[j], acc[i][j]);
        }
        __syncthreads();
    }
    if (partial) {
        const int Mtot = gridDim.y*BM, Ntot = gridDim.x*BN;
        #pragma unroll
        for (int i=0;i<TM;i++) {
            int m = bm + ty*TM + i;
            #pragma unroll
            for (int j=0;j<TN;j+=4)
                *(float4*)&partial[((size_t)blockIdx.z*Mtot + m)*Ntot + bn + tx*TN + j]
                    = *(float4*)&acc[i][j];
        }
    } else {
        #pragma unroll
        for (int i=0;i<TM;i++) {
            int gm = bm + ty*TM + i;
            #pragma unroll
            for (int j=0;j<TN;j++) {
                int gn = bn + tx*TN + j;
                float v = acc[i][j] + (bias ? bias[gn] : 0.f);
                if (RELU) v = fmaxf(v, 0.f);
                C[(size_t)gm*ldc + gn] = v;
            }
        }
    }
}

template<int BM,int BN,int BK,int TM,int TN>
__global__ void __launch_bounds__(256) gemm_nn(
    const float* __restrict__ A, int lda, long long strideA,
    const float* __restrict__ W, int ldw, long long strideW,
    const float* __restrict__ bias, int strideBias,
    float* __restrict__ C, int ldc, long long strideC,
    int K, int KS, float* __restrict__ partial)
{
    const int zb = blockIdx.z / KS, chunk = blockIdx.z % KS;
    const int Kc = K / KS;
    A += (long long)zb*strideA + chunk*Kc;
    W += (long long)zb*strideW + (size_t)chunk*Kc*ldw;
    C += (long long)zb*strideC;
    if (bias) bias += (long long)zb*strideBias;

    __shared__ float sA[BK][BM];
    __shared__ float sW[BK][BN];
    const int tid = threadIdx.x;
    const int bm = blockIdx.y*BM, bn = blockIdx.x*BN;
    const int tx = tid % (BN/TN), ty = tid / (BN/TN);
    float acc[TM][TN];
    #pragma unroll
    for (int i=0;i<TM;i++)
        #pragma unroll
        for (int j=0;j<TN;j++) acc[i][j]=0.f;

    for (int k0=0;k0<Kc;k0+=BK) {
        for (int i=tid;i<BM*(BK/4);i+=256) {
            int r=i/(BK/4), kv=i%(BK/4);
            float4 v=*(const float4*)(A+(size_t)(bm+r)*lda + k0 + kv*4);
            sA[kv*4+0][r]=v.x; sA[kv*4+1][r]=v.y; sA[kv*4+2][r]=v.z; sA[kv*4+3][r]=v.w;
        }
        for (int i=tid;i<BK*(BN/4);i+=256) {
            int kk=i/(BN/4), nv=i%(BN/4);
            *(float4*)&sW[kk][nv*4] = *(const float4*)(W+(size_t)(k0+kk)*ldw + bn + nv*4);
        }
        __syncthreads();
        #pragma unroll
        for (int kk=0;kk<BK;kk++) {
            float a[TM], w[TN];
            #pragma unroll
            for (int i=0;i<TM;i+=4) *(float4*)&a[i] = *(const float4*)&sA[kk][ty*TM+i];
            #pragma unroll
            for (int j=0;j<TN;j+=4) *(float4*)&w[j] = *(const float4*)&sW[kk][tx*TN+j];
            #pragma unroll
            for (int i=0;i<TM;i++)
                #pragma unroll
                for (int j=0;j<TN;j++) acc[i][j] = fmaf(a[i], w[j], acc[i][j]);
        }
        __syncthreads();
    }
    if (partial) {
        const int Mtot = gridDim.y*BM, Ntot = gridDim.x*BN;
        #pragma unroll
        for (int i=0;i<TM;i++) {
            int m = bm + ty*TM + i;
            #pragma unroll
            for (int j=0;j<TN;j+=4)
                *(float4*)&partial[((size_t)blockIdx.z*Mtot + m)*Ntot + bn + tx*TN + j]
                    = *(float4*)&acc[i][j];
        }
    } else {
        #pragma unroll
        for (int i=0;i<TM;i++) {
            int gm = bm + ty*TM + i;
            #pragma unroll
            for (int j=0;j<TN;j++) {
                int gn = bn + tx*TN + j;
                C[(size_t)gm*ldc + gn] = acc[i][j] + (bias ? bias[gn] : 0.f);
            }
        }
    }
}

__global__ void __launch_bounds__(256) reduce_ks(
    const float* __restrict__ partial, const float* __restrict__ bias, int strideBias,
    float* __restrict__ C, int ldc, long long strideC,
    int Mtot, int Ntot, int KS, int relu)
{
    const int zb = blockIdx.y;
    int idx = blockIdx.x*256 + threadIdx.x;
    if (idx >= Mtot*Ntot) return;
    int m = idx / Ntot, n = idx % Ntot;
    float s = 0.f;
    for (int c=0;c<KS;c++)
        s += partial[((size_t)(zb*KS+c)*Mtot + m)*Ntot + n];
    if (bias) s += bias[(size_t)zb*strideBias + n];
    if (relu) s = fmaxf(s, 0.f);
    C[(size_t)zb*strideC + (size_t)m*ldc + n] = s;
}

// =================== bf16 split conversion ======================================
__global__ void __launch_bounds__(256) conv_mem_kernel(const float* __restrict__ mem)
{
    const int row = blockIdx.x*8 + (threadIdx.x>>5);
    const int lane = threadIdx.x&31;
    const float* p = mem + (size_t)row*D_;
    __nv_bfloat16* oh = g_mb + (size_t)row*KP_;
    float ss = 0.f;
    #pragma unroll
    for (int i=0;i<12;i++) {
        int e = lane*4 + i*128;
        float4 v = *(const float4*)(p+e);
        ss += v.x*v.x + v.y*v.y + v.z*v.z + v.w*v.w;
        __nv_bfloat16 h[4], l[4];
        float f[4] = {v.x,v.y,v.z,v.w};
        #pragma unroll
        for (int c=0;c<4;c++) {
            h[c] = __float2bfloat16(f[c]);
            l[c] = __float2bfloat16(f[c] - __bfloat162float(h[c]));
        }
        *(ulonglong1*)(oh + e)       = *(ulonglong1*)h;
        *(ulonglong1*)(oh + D_ + e)  = *(ulonglong1*)l;
    }
    for (int o=16;o;o>>=1) ss += __shfl_xor_sync(~0u, ss, o);
    if (lane==0) g_nm[row] = sqrtf(ss);
}

__global__ void __launch_bounds__(256) conv_a_kernel()
{
    const int row = blockIdx.x*8 + (threadIdx.x>>5);
    const int lane = threadIdx.x&31;
    const float sc = (row < B_) ? rsqrtf((float)D_) : 1.0f;
    const float* p = (row < B_) ? (g_qt + (size_t)row*D_) : (g_xsq + (size_t)(row-B_)*D_);
    __nv_bfloat16* oh = g_ab + (size_t)row*KP_;
    #pragma unroll
    for (int i=0;i<12;i++) {
        int e = lane*4 + i*128;
        float4 v = *(const float4*)(p+e);
        float f[4] = {v.x*sc, v.y*sc, v.z*sc, v.w*sc};
        __nv_bfloat16 h[4], l[4];
        #pragma unroll
        for (int c=0;c<4;c++) {
            h[c] = __float2bfloat16(f[c]);
            l[c] = __float2bfloat16(f[c] - __bfloat162float(h[c]));
        }
        *(ulonglong1*)(oh + e)      = *(ulonglong1*)h;
        *(ulonglong1*)(oh + D_ + e) = *(ulonglong1*)l;
    }
}

// =================== big tensor-core GEMM: 3-product bf16 split =================
// g_S = A*Mem^T computed as Ah*Bh + Ah*Bl + Al*Bh (drop Al*Bl ~2^-18).
// Segment s of the K'=3*D loop: Aoff = (s==2 ? D : 0), Boff = (s==1 ? D : 0).
#define LDSM4(R0,R1,R2,R3,ADDR) \
    asm volatile("ldmatrix.sync.aligned.m8n8.x4.shared.b16 {%0,%1,%2,%3}, [%4];" \
        : "=r"(R0),"=r"(R1),"=r"(R2),"=r"(R3) : "r"(ADDR))
#define MMA16816(D,A,B0,B1) \
    asm volatile("mma.sync.aligned.m16n8k16.row.col.f32.bf16.bf16.f32 " \
        "{%0,%1,%2,%3}, {%4,%5,%6,%7}, {%8,%9}, {%0,%1,%2,%3};" \
        : "+f"((D)[0]),"+f"((D)[1]),"+f"((D)[2]),"+f"((D)[3]) \
        : "r"((A)[0]),"r"((A)[1]),"r"((A)[2]),"r"((A)[3]),"r"(B0),"r"(B1))

#define SLD 40   // smem row stride in bf16 elems (80B)
#define SEGC 48  // 32-wide k-chunks per D-segment (1536/32)

__global__ void __launch_bounds__(256) bigmm_kernel()
{
    __shared__ __align__(16) __nv_bfloat16 sA[2][128*SLD];
    __shared__ __align__(16) __nv_bfloat16 sB[2][128*SLD];
    const int tid = threadIdx.x;
    const int warp = tid>>5, lane = tid&31;
    const int wm = warp>>2, wn = warp&3;                  // 2 x 4 warps
    const int nbase = blockIdx.x*128, mbase = blockIdx.y*128;

    float acc[4][4][4];
    #pragma unroll
    for (int i=0;i<4;i++)
        #pragma unroll
        for (int j=0;j<4;j++)
            #pragma unroll
            for (int c=0;c<4;c++) acc[i][j][c]=0.f;

    const int r0 = tid>>1;            // 0..127
    const int seg0 = (tid&1)*2;       // 0 or 2

    #define LOAD_TILES(BUF,KC) do {                                              \
        int seg_ = (KC)/SEGC;                                                     \
        int k0_  = ((KC)%SEGC)*32;                                                \
        int aOff_ = (seg_==2) ? D_ : 0;                                           \
        int bOff_ = (seg_==1) ? D_ : 0;                                           \
        _Pragma("unroll")                                                        \
        for (int i=0;i<2;i++) {                                                  \
            int seg = seg0 + i;                                                  \
            uint32_t sa_ = (uint32_t)__cvta_generic_to_shared(                   \
                &sA[BUF][r0*SLD + seg*8]);                                       \
            const void* ga_ = g_ab + (size_t)(mbase+r0)*KP_ + aOff_ + k0_ + seg*8;\
            asm volatile("cp.async.ca.shared.global [%0], [%1], 16;"             \
                :: "r"(sa_), "l"(ga_));                                          \
            uint32_t sb_ = (uint32_t)__cvta_generic_to_shared(                   \
                &sB[BUF][r0*SLD + seg*8]);                                       \
            const void* gb_ = g_mb + (size_t)(nbase+r0)*KP_ + bOff_ + k0_ + seg*8;\
            asm volatile("cp.async.ca.shared.global [%0], [%1], 16;"             \
                :: "r"(sb_), "l"(gb_));                                          \
        }                                                                        \
        asm volatile("cp.async.commit_group;");                                  \
    } while(0)

    LOAD_TILES(0, 0);
    const int KC = 3*SEGC;   // 144 chunks of 32 over K' = 3*D
    for (int kc=0; kc<KC; kc++) {
        int buf = kc & 1;
        asm volatile("cp.async.wait_group 0;");
        __syncthreads();
        if (kc+1 < KC) LOAD_TILES(buf^1, kc+1);
        #pragma unroll
        for (int kk=0; kk<2; kk++) {
            const int kb = kk*16;
            uint32_t a[4][4], b[4][2];
            #pragma unroll
            for (int mf=0; mf<4; mf++) {
                int row = wm*64 + mf*16 + (lane&15);
                int ko  = kb + ((lane>>4)<<3);
                uint32_t ad = (uint32_t)__cvta_generic_to_shared(&sA[buf][row*SLD + ko]);
                LDSM4(a[mf][0],a[mf][1],a[mf][2],a[mf][3], ad);
            }
            #pragma unroll
            for (int p=0; p<2; p++) {
                int nrow = wn*32 + p*16 + ((lane>>4)<<3) + (lane&7);
                int ko   = kb + (((lane>>3)&1)<<3);
                uint32_t ad = (uint32_t)__cvta_generic_to_shared(&sB[buf][nrow*SLD + ko]);
                LDSM4(b[2*p][0],b[2*p][1],b[2*p+1][0],b[2*p+1][1], ad);
            }
            #pragma unroll
            for (int mf=0; mf<4; mf++)
                #pragma unroll
                for (int nf=0; nf<4; nf++)
                    MMA16816(acc[mf][nf], a[mf], b[nf][0], b[nf][1]);
        }
        __syncthreads();
    }
    #pragma unroll
    for (int mf=0; mf<4; mf++) {
        int m = mbase + wm*64 + mf*16 + (lane>>2);
        #pragma unroll
        for (int nf=0; nf<4; nf++) {
            int n = nbase + wn*32 + nf*8 + ((lane&3)<<1);
            *(float2*)&g_S[(size_t)m*BS_ + n]     = make_float2(acc[mf][nf][0], acc[mf][nf][1]);
            *(float2*)&g_S[(size_t)(m+8)*BS_ + n] = make_float2(acc[mf][nf][2], acc[mf][nf][3]);
        }
    }
}

// =================== LayerNorm / CA / softmax / reduce ==========================
__global__ void __launch_bounds__(256) ln_kernel(
    const float* __restrict__ a, const float* __restrict__ r,
    const float* __restrict__ w, const float* __restrict__ bb,
    float* __restrict__ out, float* __restrict__ norm_out)
{
    const int row = blockIdx.x, tid = threadIdx.x;
    const float* ap = a + (size_t)row*D_;
    const float* rp = r ? r + (size_t)row*D_ : nullptr;
    float vals[6]; float s1=0.f, s2=0.f;
    #pragma unroll
    for (int i=0;i<6;i++) {
        int e = tid + i*256;
        float v = ap[e] + (rp ? rp[e] : 0.f);
        vals[i]=v; s1+=v; s2+=v*v;
    }
    __shared__ float red[16];
    int lane=tid&31, wid=tid>>5;
    for (int o=16;o;o>>=1){ s1+=__shfl_xor_sync(~0u,s1,o); s2+=__shfl_xor_sync(~0u,s2,o); }
    if (lane==0){ red[wid]=s1; red[8+wid]=s2; }
    __syncthreads();
    if (tid==0){ float a1=0,a2=0; for(int k=0;k<8;k++){a1+=red[k];a2+=red[8+k];} red[0]=a1; red[8]=a2; }
    __syncthreads();
    float mean = red[0]*(1.0f/D_);
    float var  = red[8]*(1.0f/D_) - mean*mean;
    float rstd = rsqrtf(var + 1e-5f);
    float ss = 0.f;
    #pragma unroll
    for (int i=0;i<6;i++) {
        int e = tid + i*256;
        float y = (vals[i]-mean)*rstd*w[e] + bb[e];
        out[(size_t)row*D_+e] = y;
        ss += y*y;
    }
    if (norm_out) {
        for (int o=16;o;o>>=1) ss+=__shfl_xor_sync(~0u,ss,o);
        __syncthreads();
        if (lane==0) red[wid]=ss;
        __syncthreads();
        if (tid==0){ float t=0; for(int k=0;k<8;k++) t+=red[k]; norm_out[row]=sqrtf(t); }
    }
}

__global__ void __launch_bounds__(256) ca_scores_kernel(const float* __restrict__ mem)
{
    __shared__ float gs[NH_*D_];
    const int b = blockIdx.x, tid = threadIdx.x;
    const float4* gsrc = (const float4*)(g_g + (size_t)b*NH_*D_);
    for (int i=tid;i<NH_*D_/4;i+=256) ((float4*)gs)[i]=gsrc[i];
    __syncthreads();
    const int warp=tid>>5, lane=tid&31;
    const float* mb = mem + (size_t)b*S_*D_;
    const float scale = rsqrtf((float)DH_);
    const int sbase = blockIdx.y*128 + warp*16;
    for (int grp=0;grp<4;grp++) {
        int s0 = sbase + grp*4;
        float acc[NH_][4];
        #pragma unroll
        for (int h=0;h<NH_;h++)
            #pragma unroll
            for (int r2=0;r2<4;r2++) acc[h][r2]=0.f;
        #pragma unroll
        for (int i=0;i<12;i++) {
            int e = lane*4 + i*128;
            float4 m[4];
            #pragma unroll
            for (int r2=0;r2<4;r2++) m[r2]=*(const float4*)(mb+(size_t)(s0+r2)*D_+e);
            #pragma unroll
            for (int h=0;h<NH_;h++) {
                float4 gv=*(const float4*)(gs + h*D_ + e);
                #pragma unroll
                for (int r2=0;r2<4;r2++)
                    acc[h][r2] += gv.x*m[r2].x + gv.y*m[r2].y + gv.z*m[r2].z + gv.w*m[r2].w;
            }
        }
        #pragma unroll
        for (int h=0;h<NH_;h++)
            #pragma unroll
            for (int r2=0;r2<4;r2++) {
                float v=acc[h][r2];
                for (int o=16;o;o>>=1) v+=__shfl_xor_sync(~0u,v,o);
                if (lane==0) g_scores[((size_t)b*NH_+h)*S_ + s0+r2] = v*scale;
            }
    }
}

__global__ void __launch_bounds__(256) ca_softmax_kernel()
{
    const int row=blockIdx.x, tid=threadIdx.x;
    float* sp = g_scores + (size_t)row*S_;
    float v = sp[tid];
    __shared__ float red[16];
    int lane=tid&31, wid=tid>>5;
    float m=v;
    for (int o=16;o;o>>=1) m=fmaxf(m,__shfl_xor_sync(~0u,m,o));
    if (lane==0) red[wid]=m;
    __syncthreads();
    if (tid==0){ float mm=red[0]; for(int k=1;k<8;k++) mm=fmaxf(mm,red[k]); red[0]=mm; }
    __syncthreads();
    m=red[0];
    float e=__expf(v-m);
    float s=e;
    for (int o=16;o;o>>=1) s+=__shfl_xor_sync(~0u,s,o);
    __syncthreads();
    if (lane==0) red[8+wid]=s;
    __syncthreads();
    if (tid==0){ float t=0; for(int k=0;k<8;k++) t+=red[8+k]; red[8]=t; }
    __syncthreads();
    sp[tid]=e/red[8];
}

__global__ void __launch_bounds__(256) mtilde_kernel(const float* __restrict__ mem)
{
    __shared__ float at[NH_*S_];
    const int b=blockIdx.x, tid=threadIdx.x;
    for (int i=tid;i<NH_*S_;i+=256) at[i]=g_scores[(size_t)b*NH_*S_+i];
    __syncthreads();
    const int e = blockIdx.y*512 + tid*2;
    const float* mb = mem + (size_t)b*S_*D_;
    float2 acc[NH_];
    #pragma unroll
    for (int h=0;h<NH_;h++){ acc[h].x=0.f; acc[h].y=0.f; }
    for (int s=0;s<S_;s++) {
        float2 mv=*(const float2*)(mb+(size_t)s*D_+e);
        #pragma unroll
        for (int h=0;h<NH_;h++){
            float a=at[h*S_+s];
            acc[h].x=fmaf(a,mv.x,acc[h].x);
            acc[h].y=fmaf(a,mv.y,acc[h].y);
        }
    }
    #pragma unroll
    for (int h=0;h<NH_;h++)
        *(float2*)(g_mt + (size_t)b*NH_*D_ + h*D_ + e) = acc[h];
}

__global__ void __launch_bounds__(256) pool_reduce_kernel(
    const float* __restrict__ ls, float* __restrict__ out)
{
    const int j=blockIdx.x, i=blockIdx.y, s=threadIdx.x;
    float Sv = g_S[(size_t)i*BS_ + j*S_ + s];
    float Cv = g_S[(size_t)(B_+i)*BS_ + j*S_ + s];
    float nmv = g_nm[j*S_+s];
    __shared__ float red[16];
    int lane=s&31, wid=s>>5;
    float m=Sv;
    for (int o=16;o;o>>=1) m=fmaxf(m,__shfl_xor_sync(~0u,m,o));
    if (lane==0) red[wid]=m;
    __syncthreads();
    if (s==0){ float mm=red[0]; for(int k=1;k<8;k++) mm=fmaxf(mm,red[k]); red[0]=mm; }
    __syncthreads();
    m=red[0];
    float e = expf(Sv-m);
    float t1=e, t2=e*Cv/nmv;
    for (int o=16;o;o>>=1){ t1+=__shfl_xor_sync(~0u,t1,o); t2+=__shfl_xor_sync(~0u,t2,o); }
    __syncthreads();
    if (lane==0){ red[wid]=t1; red[8+wid]=t2; }
    __syncthreads();
    if (s==0) {
        float Z=0.f, Wv=0.f;
        for (int k=0;k<8;k++){ Z+=red[k]; Wv+=red[8+k]; }
        float val = expf(ls[0]) * Wv / (Z * g_nx[i]);
        out[(size_t)i*B_ + j] = val;
        out[(size_t)B_*B_ + (size_t)j*B_ + i] = val;
    }
}

__global__ void copy_xsq_kernel(float* __restrict__ out)
{
    int idx = blockIdx.x*256 + threadIdx.x;
    out[(size_t)2*B_*B_ + idx] = g_xsq[idx];
}

// =================== host =======================================================
template<typename T> static float* sym(T& s){ void* p=nullptr; cudaGetSymbolAddress(&p, s); return (float*)p; }

extern "C" void kernel_launch(void* const* d_in, const int* in_sizes, int n_in,
                              void* d_out, int out_size)
{
    const float* x        =(const float*)d_in[0];
    const float* mem      =(const float*)d_in[1];
    const float* emb_w    =(const float*)d_in[2];
    const float* emb_b    =(const float*)d_in[3];
    const float* sa_in_w  =(const float*)d_in[4];
    const float* sa_in_b  =(const float*)d_in[5];
    const float* sa_out_w =(const float*)d_in[6];
    const float* sa_out_b =(const float*)d_in[7];
    const float* ca_in_w  =(const float*)d_in[8];
    const float* ca_in_b  =(const float*)d_in[9];
    const float* ca_out_w =(const float*)d_in[10];
    const float* ca_out_b =(const float*)d_in[11];
    const float* lin1_w   =(const float*)d_in[12];
    const float* lin1_b   =(const float*)d_in[13];
    const float* lin2_w   =(const float*)d_in[14];
    const float* lin2_b   =(const float*)d_in[15];
    const float* ln1_w    =(const float*)d_in[16];
    const float* ln1_b    =(const float*)d_in[17];
    const float* ln2_w    =(const float*)d_in[18];
    const float* ln2_b    =(const float*)d_in[19];
    const float* ln3_w    =(const float*)d_in[20];
    const float* ln3_b    =(const float*)d_in[21];
    const float* fin_w    =(const float*)d_in[22];
    const float* fin_b    =(const float*)d_in[23];
    const float* attn_in_w=(const float*)d_in[24];
    const float* attn_in_b=(const float*)d_in[25];
    const float* logit_sc =(const float*)d_in[26];
    float* out = (float*)d_out;

    float* t0 = sym(g_t0);  float* v   = sym(g_v);   float* sa  = sym(g_sa);
    float* t1 = sym(g_t1);  float* qp  = sym(g_qp);  float* gg  = sym(g_g);
    float* mt = sym(g_mt);  float* o   = sym(g_o);   float* ca  = sym(g_ca);
    float* t2 = sym(g_t2);  float* h1  = sym(g_h1);  float* ff  = sym(g_ff);
    float* t3 = sym(g_t3);  float* xsq = sym(g_xsq); float* qp2 = sym(g_qp2);
    float* qt = sym(g_qt);  float* nx  = sym(g_nx);  float* pt  = sym(g_part);

    const float* NOB = nullptr;

    // 0. memory -> bf16 hi/lo + row norms
    conv_mem_kernel<<<BS_/8, 256>>>(mem);

    // 1. t0 = x @ emb_w.T + emb_b  (K=768, KS=4)
    gemm_nt<64,64,16,4,4,false><<<dim3(D_/64, B_/64, 4), 256>>>(
        x, DIN_, 0, emb_w, DIN_, 0, NOB, 0, nullptr, 0, 0, DIN_, 4, pt);
    reduce_ks<<<dim3((B_*D_+255)/256, 1), 256>>>(pt, emb_b, 0, t0, D_, 0, B_, D_, 4, 0);

    // 2. SA (L=1): v = t0 @ wv.T + bv ; sa = v @ out_w.T + out_b   (KS=6)
    gemm_nt<64,64,16,4,4,false><<<dim3(D_/64, B_/64, 6), 256>>>(
        t0, D_, 0, sa_in_w + (size_t)2*D_*D_, D_, 0, NOB, 0, nullptr, 0, 0, D_, 6, pt);
    reduce_ks<<<dim3((B_*D_+255)/256, 1), 256>>>(pt, sa_in_b + 2*D_, 0, v, D_, 0, B_, D_, 6, 0);
    gemm_nt<64,64,16,4,4,false><<<dim3(D_/64, B_/64, 6), 256>>>(
        v, D_, 0, sa_out_w, D_, 0, NOB, 0, nullptr, 0, 0, D_, 6, pt);
    reduce_ks<<<dim3((B_*D_+255)/256, 1), 256>>>(pt, sa_out_b, 0, sa, D_, 0, B_, D_, 6, 0);

    // 3. t1 = LN(t0 + sa)
    ln_kernel<<<B_, 256>>>(t0, sa, ln1_w, ln1_b, t1, nullptr);

    // 4. CA q-proj (KS=6), then g[b,h] = qp_h @ wk_h (batched heads, K=192)
    gemm_nt<64,64,16,4,4,false><<<dim3(D_/64, B_/64, 6), 256>>>(
        t1, D_, 0, ca_in_w, D_, 0, NOB, 0, nullptr, 0, 0, D_, 6, pt);
    reduce_ks<<<dim3((B_*D_+255)/256, 1), 256>>>(pt, ca_in_b, 0, qp, D_, 0, B_, D_, 6, 0);
    gemm_nn<64,64,16,4,4><<<dim3(D_/64, B_/64, NH_), 256>>>(
        qp, D_, DH_, ca_in_w + (size_t)D_*D_, D_, (long long)DH_*D_,
        NOB, 0, gg, NH_*D_, D_, DH_, 1, nullptr);

    // 5. CA scores / softmax / weighted memory
    ca_scores_kernel<<<dim3(B_,2), 256>>>(mem);
    ca_softmax_kernel<<<B_*NH_, 256>>>();
    mtilde_kernel<<<dim3(B_,3), 256>>>(mem);

    // 6. o_h = m~_h @ wv_h.T + bv_h (batched heads, KS=6); ca = o @ out_w.T + out_b
    gemm_nt<64,64,16,4,4,false><<<dim3(DH_/64, B_/64, NH_*6), 256>>>(
        mt, NH_*D_, D_, ca_in_w + (size_t)2*D_*D_, D_, (long long)DH_*D_,
        NOB, 0, nullptr, 0, 0, D_, 6, pt);
    reduce_ks<<<dim3((B_*DH_+255)/256, NH_), 256>>>(pt, ca_in_b + 2*D_, DH_, o, D_, DH_, B_, DH_, 6, 0);
    gemm_nt<64,64,16,4,4,false><<<dim3(D_/64, B_/64, 6), 256>>>(
        o, D_, 0, ca_out_w, D_, 0, NOB, 0, nullptr, 0, 0, D_, 6, pt);
    reduce_ks<<<dim3((B_*D_+255)/256, 1), 256>>>(pt, ca_out_b, 0, ca, D_, 0, B_, D_, 6, 0);

    // 7. t2 = LN(t1 + ca)
    ln_kernel<<<B_, 256>>>(t1, ca, ln2_w, ln2_b, t2, nullptr);

    // 8. FF
    gemm_nt<64,64,16,4,4,false><<<dim3(FF_/64, B_/64, 4), 256>>>(
        t2, D_, 0, lin1_w, D_, 0, NOB, 0, nullptr, 0, 0, D_, 4, pt);
    reduce_ks<<<dim3((B_*FF_+255)/256, 1), 256>>>(pt, lin1_b, 0, h1, FF_, 0, B_, FF_, 4, 1);
    gemm_nt<64,64,16,4,4,false><<<dim3(D_/64, B_/64, 4), 256>>>(
        h1, FF_, 0, lin2_w, FF_, 0, NOB, 0, nullptr, 0, 0, FF_, 4, pt);
    reduce_ks<<<dim3((B_*D_+255)/256, 1), 256>>>(pt, lin2_b, 0, ff, D_, 0, B_, D_, 4, 0);

    // 9. t3 = LN(t2 + ff) ; x_sq = LN(t3) with row norm
    ln_kernel<<<B_, 256>>>(t2, ff, ln3_w, ln3_b, t3, nullptr);
    ln_kernel<<<B_, 256>>>(t3, nullptr, fin_w, fin_b, xsq, nx);

    // 10. pooling projections
    gemm_nt<64,64,16,4,4,false><<<dim3(D_/64, B_/64, 6), 256>>>(
        xsq, D_, 0, attn_in_w, D_, 0, NOB, 0, nullptr, 0, 0, D_, 6, pt);
    reduce_ks<<<dim3((B_*D_+255)/256, 1), 256>>>(pt, attn_in_b, 0, qp2, D_, 0, B_, D_, 6, 0);
    gemm_nn<64,64,16,4,4><<<dim3(D_/64, B_/64, 6), 256>>>(
        qp2, D_, 0, attn_in_w + (size_t)D_*D_, D_, 0,
        NOB, 0, nullptr, 0, 0, D_, 6, pt);
    reduce_ks<<<dim3((B_*D_+255)/256, 1), 256>>>(pt, NOB, 0, qt, D_, 0, B_, D_, 6, 0);

    // 11. A -> bf16 hi/lo ; big tensor GEMM (3-product split, K'=4608)
    conv_a_kernel<<<32, 256>>>();
    bigmm_kernel<<<dim3(BS_/128, 2), 256>>>();

    // 12. final softmax-weighted cosine reduce; third output
    pool_reduce_kernel<<<dim3(B_, B_), 256>>>(logit_sc, out);
    copy_xsq_kernel<<<(B_*D_)/256, 256>>>(out);

    (void)in_sizes; (void)n_in; (void)out_size;
}